// round 2
// baseline (speedup 1.0000x reference)
#include <cuda_runtime.h>
#include <cuda_fp16.h>
#include <cstdint>

#define IN_F  4096
#define OUT_F 4096
#define MTOT  2048

// fp16 scratch (device globals: no allocation in kernel_launch)
__device__ __half g_wh[(size_t)OUT_F * IN_F];   // w_q * s_w, [o, k] K-major
__device__ __half g_xh[(size_t)MTOT  * IN_F];   // permuted x, [m, k] K-major

// ------------------------------------------------------------------ helpers
__device__ __forceinline__ uint32_t smem_u32(const void* p) {
    uint32_t a;
    asm("{ .reg .u64 t; cvta.to.shared.u64 t, %1; cvt.u32.u64 %0, t; }" : "=r"(a) : "l"(p));
    return a;
}

// 128B-row swizzle: XOR 16B-chunk index with row (bits 7..9 -> bits 4..6)
__device__ __forceinline__ uint32_t sw128(uint32_t off) { return off ^ ((off >> 3) & 0x70); }

__device__ __forceinline__ void cpa16(uint32_t dst, const void* src) {
    asm volatile("cp.async.cg.shared.global [%0], [%1], 16;" :: "r"(dst), "l"(src));
}

#define LDSM4(r0, r1, r2, r3, addr) \
    asm volatile("ldmatrix.sync.aligned.m8n8.x4.shared.b16 {%0,%1,%2,%3}, [%4];" \
        : "=r"(r0), "=r"(r1), "=r"(r2), "=r"(r3) : "r"(addr))

#define MMA16816(d0, d1, d2, d3, a0, a1, a2, a3, b0, b1) \
    asm volatile("mma.sync.aligned.m16n8k16.row.col.f32.f16.f16.f32 " \
        "{%0,%1,%2,%3},{%4,%5,%6,%7},{%8,%9},{%0,%1,%2,%3};" \
        : "+f"(d0), "+f"(d1), "+f"(d2), "+f"(d3) \
        : "r"(a0), "r"(a1), "r"(a2), "r"(a3), "r"(b0), "r"(b1))

// ---------------------------------------------------------- prep_w: w_q * s_w -> fp16
__global__ void __launch_bounds__(256) prep_w_kernel(const int* __restrict__ wq,
                                                     const float* __restrict__ sw) {
    unsigned gid = blockIdx.x * 256u + threadIdx.x;     // 2M threads, 8 elems each
    unsigned o  = gid >> 9;
    unsigned k0 = (gid & 511u) << 3;
    float s = sw[(k0 >> 7) * OUT_F + o];
    const int4* p = reinterpret_cast<const int4*>(wq + (size_t)o * IN_F + k0);
    int4 a = p[0], b = p[1];
    __half2 h0 = __floats2half2_rn(a.x * s, a.y * s);
    __half2 h1 = __floats2half2_rn(a.z * s, a.w * s);
    __half2 h2 = __floats2half2_rn(b.x * s, b.y * s);
    __half2 h3 = __floats2half2_rn(b.z * s, b.w * s);
    uint4 v;
    v.x = *reinterpret_cast<uint32_t*>(&h0);
    v.y = *reinterpret_cast<uint32_t*>(&h1);
    v.z = *reinterpret_cast<uint32_t*>(&h2);
    v.w = *reinterpret_cast<uint32_t*>(&h3);
    *reinterpret_cast<uint4*>(g_wh + (size_t)o * IN_F + k0) = v;
}

// ---------------------------------------------------------- prep_x: permute + fp32->fp16
__global__ void __launch_bounds__(256) prep_x_kernel(const float* __restrict__ x,
                                                     const int* __restrict__ perm32) {
    __shared__ float row[IN_F];
    __shared__ int is64s;
    int m = blockIdx.x, tid = threadIdx.x;
    const float4* src = reinterpret_cast<const float4*>(x + (size_t)m * IN_F);
#pragma unroll
    for (int i = 0; i < 4; ++i)
        reinterpret_cast<float4*>(row)[tid + i * 256] = src[tid + i * 256];
    if (tid == 0) {
        // jnp int64 vs int32 detection: int64 LE => odd 32-bit words all zero.
        // (A permutation can't have 16 consecutive odd entries == 0 in int32.)
        int acc = 0;
#pragma unroll
        for (int t = 1; t < 32; t += 2) acc |= perm32[t];
        is64s = (acc == 0) ? 1 : 0;
    }
    __syncthreads();
    const int sh = is64s;
    const int j0 = tid * 16;
    __half* dst = g_xh + (size_t)m * IN_F + j0;
#pragma unroll
    for (int h = 0; h < 2; ++h) {
        int jb = j0 + h * 8;
        float v[8];
#pragma unroll
        for (int i = 0; i < 8; ++i) v[i] = row[perm32[(jb + i) << sh]];
        __half2 p0 = __floats2half2_rn(v[0], v[1]);
        __half2 p1 = __floats2half2_rn(v[2], v[3]);
        __half2 p2 = __floats2half2_rn(v[4], v[5]);
        __half2 p3 = __floats2half2_rn(v[6], v[7]);
        uint4 u;
        u.x = *reinterpret_cast<uint32_t*>(&p0);
        u.y = *reinterpret_cast<uint32_t*>(&p1);
        u.z = *reinterpret_cast<uint32_t*>(&p2);
        u.w = *reinterpret_cast<uint32_t*>(&p3);
        *reinterpret_cast<uint4*>(dst + h * 8) = u;
    }
}

// ---------------------------------------------------------- GEMM: mma.sync (HMMA) f16->f32
// CTA tile 128(M) x 128(N) x 64(K). 256 threads = 8 warps in 2(M) x 4(N), warp tile 64x32.
// 3-stage cp.async pipeline. Stage = A(16KB) + B(16KB) = 32KB; 96KB total -> 2 CTAs/SM.
static constexpr int BK          = 64;
static constexpr int NITER       = IN_F / BK;       // 64
static constexpr uint32_t STAGE_BYTES = 32768;
static constexpr uint32_t GEMM_SMEM   = 3 * STAGE_BYTES;  // 98304

// Load one K-slice: A rows [m0,m0+128), B rows [n0,n0+128), cols [j*64, j*64+64)
__device__ __forceinline__ void load_stage(uint32_t sb, int m0, int n0, int j, int tid) {
    const int k0 = j * BK;
#pragma unroll
    for (int c = 0; c < 4; ++c) {                 // A: 128 rows x 8 chunks of 16B
        int idx = tid + c * 256;
        int row = idx >> 3, ch = idx & 7;
        cpa16(sb + sw128((uint32_t)row * 128u + (uint32_t)ch * 16u),
              g_xh + (size_t)(m0 + row) * IN_F + k0 + ch * 8);
    }
#pragma unroll
    for (int c = 0; c < 4; ++c) {                 // B
        int idx = tid + c * 256;
        int row = idx >> 3, ch = idx & 7;
        cpa16(sb + 16384u + sw128((uint32_t)row * 128u + (uint32_t)ch * 16u),
              g_wh + (size_t)(n0 + row) * IN_F + k0 + ch * 8);
    }
}

__device__ __forceinline__ void compute_stage(uint32_t sA, uint32_t sB,
                                              int arow_l, int a_c, int brow_l, int b_c,
                                              int wm, int wn, float acc[4][4][4]) {
#pragma unroll
    for (int ks = 0; ks < 4; ++ks) {              // 4 k-steps of 16
        uint32_t a[4][4], b[2][4];
#pragma unroll
        for (int mi = 0; mi < 4; ++mi) {
            uint32_t off = (uint32_t)((wm * 64 + mi * 16 + arow_l) * 128 + (ks * 2 + a_c) * 16);
            LDSM4(a[mi][0], a[mi][1], a[mi][2], a[mi][3], sA + sw128(off));
        }
#pragma unroll
        for (int nb = 0; nb < 2; ++nb) {
            uint32_t off = (uint32_t)((wn * 32 + nb * 16 + brow_l) * 128 + (ks * 2 + b_c) * 16);
            LDSM4(b[nb][0], b[nb][1], b[nb][2], b[nb][3], sB + sw128(off));
        }
#pragma unroll
        for (int mi = 0; mi < 4; ++mi)
#pragma unroll
            for (int ni = 0; ni < 4; ++ni) {
                uint32_t b0 = b[ni >> 1][(ni & 1) * 2];
                uint32_t b1 = b[ni >> 1][(ni & 1) * 2 + 1];
                MMA16816(acc[mi][ni][0], acc[mi][ni][1], acc[mi][ni][2], acc[mi][ni][3],
                         a[mi][0], a[mi][1], a[mi][2], a[mi][3], b0, b1);
            }
    }
}

__global__ void __launch_bounds__(256, 2) gemm_kernel(const float* __restrict__ bias,
                                                      float* __restrict__ out) {
    extern __shared__ char smem[];
    const uint32_t sbase = smem_u32(smem);
    const int tid  = threadIdx.x;
    const int lane = tid & 31, wid = tid >> 5;
    const int wm = wid & 1, wn = wid >> 1;        // 2 x 4 warp grid
    const int n0 = blockIdx.x * 128, m0 = blockIdx.y * 128;

    // ldmatrix per-lane addressing constants
    // A (m16k16 regions): lanes 0-7 rows 0-7 @k0 | 8-15 rows 8-15 @k0 | 16-23 rows 0-7 @k8 | 24-31 rows 8-15 @k8
    const int arow_l = (lane & 7) + ((lane >> 3) & 1) * 8;
    const int a_c    = lane >> 4;
    // B (k16n16 regions, [n][k] layout): 0-7 n0-7@k0 | 8-15 n0-7@k8 | 16-23 n8-15@k0 | 24-31 n8-15@k8
    const int brow_l = (lane & 7) + ((lane >> 4) & 1) * 8;
    const int b_c    = (lane >> 3) & 1;

    float acc[4][4][4];
#pragma unroll
    for (int i = 0; i < 4; ++i)
#pragma unroll
        for (int j = 0; j < 4; ++j)
#pragma unroll
            for (int q = 0; q < 4; ++q) acc[i][j][q] = 0.f;

    // prologue: stages 0, 1
    load_stage(sbase + 0 * STAGE_BYTES, m0, n0, 0, tid);
    asm volatile("cp.async.commit_group;" ::: "memory");
    load_stage(sbase + 1 * STAGE_BYTES, m0, n0, 1, tid);
    asm volatile("cp.async.commit_group;" ::: "memory");

    for (int it = 0; it < NITER; ++it) {
        asm volatile("cp.async.wait_group 1;" ::: "memory");
        __syncthreads();
        const int j = it + 2;
        if (j < NITER)
            load_stage(sbase + (uint32_t)(j % 3) * STAGE_BYTES, m0, n0, j, tid);
        asm volatile("cp.async.commit_group;" ::: "memory");   // one group per iter (maybe empty)

        const uint32_t sb = sbase + (uint32_t)(it % 3) * STAGE_BYTES;
        compute_stage(sb, sb + 16384u, arow_l, a_c, brow_l, b_c, wm, wn, acc);
    }

    // epilogue: bias + float2 stores
    const int ncol = n0 + wn * 32 + (lane & 3) * 2;
    float2 bv[4];
#pragma unroll
    for (int ni = 0; ni < 4; ++ni)
        bv[ni] = *reinterpret_cast<const float2*>(bias + ncol + ni * 8);
    const int mrow = m0 + wm * 64 + (lane >> 2);
#pragma unroll
    for (int mi = 0; mi < 4; ++mi) {
        float* r0 = out + (size_t)(mrow + mi * 16) * OUT_F;
        float* r1 = r0 + 8 * OUT_F;
#pragma unroll
        for (int ni = 0; ni < 4; ++ni) {
            float2 v0, v1;
            v0.x = acc[mi][ni][0] + bv[ni].x;
            v0.y = acc[mi][ni][1] + bv[ni].y;
            v1.x = acc[mi][ni][2] + bv[ni].x;
            v1.y = acc[mi][ni][3] + bv[ni].y;
            *reinterpret_cast<float2*>(r0 + ncol + ni * 8) = v0;
            *reinterpret_cast<float2*>(r1 + ncol + ni * 8) = v1;
        }
    }
}

// ---------------------------------------------------------- launch
extern "C" void kernel_launch(void* const* d_in, const int* in_sizes, int n_in,
                              void* d_out, int out_size) {
    const float* x    = (const float*)d_in[0];
    const int*   wq   = (const int*)d_in[1];
    const float* sw   = (const float*)d_in[2];
    const int*   perm = (const int*)d_in[3];   // int32 or int64 — detected on device
    const float* bias = (const float*)d_in[4];
    float* out = (float*)d_out;

    prep_w_kernel<<<(OUT_F * (IN_F / 8)) / 256, 256>>>(wq, sw);   // 8192 blocks
    prep_x_kernel<<<MTOT, 256>>>(x, perm);

    cudaFuncSetAttribute(gemm_kernel, cudaFuncAttributeMaxDynamicSharedMemorySize, GEMM_SMEM);
    gemm_kernel<<<dim3(OUT_F / 128, MTOT / 128), 256, GEMM_SMEM>>>(bias, out);
}

// round 3
// speedup vs baseline: 1.0304x; 1.0304x over previous
#include <cuda_runtime.h>
#include <cuda_fp16.h>
#include <cstdint>

#define IN_F  4096
#define OUT_F 4096
#define MTOT  2048

// fp16 scratch (device globals: no allocation in kernel_launch)
__device__ __half g_wh[(size_t)OUT_F * IN_F];   // w_q * s_w, [o, k] K-major
__device__ __half g_xh[(size_t)MTOT  * IN_F];   // permuted x, [m, k] K-major

// ------------------------------------------------------------------ helpers
__device__ __forceinline__ uint32_t smem_u32(const void* p) {
    uint32_t a;
    asm("{ .reg .u64 t; cvta.to.shared.u64 t, %1; cvt.u32.u64 %0, t; }" : "=r"(a) : "l"(p));
    return a;
}

// 128B-row swizzle: XOR 16B-chunk index with row (bits 7..9 -> bits 4..6)
__device__ __forceinline__ uint32_t sw128(uint32_t off) { return off ^ ((off >> 3) & 0x70); }

__device__ __forceinline__ void cpa16(uint32_t dst, const void* src) {
    asm volatile("cp.async.cg.shared.global [%0], [%1], 16;" :: "r"(dst), "l"(src));
}

#define LDSM4(r0, r1, r2, r3, addr) \
    asm volatile("ldmatrix.sync.aligned.m8n8.x4.shared.b16 {%0,%1,%2,%3}, [%4];" \
        : "=r"(r0), "=r"(r1), "=r"(r2), "=r"(r3) : "r"(addr))

#define MMA16816(d0, d1, d2, d3, a0, a1, a2, a3, b0, b1) \
    asm volatile("mma.sync.aligned.m16n8k16.row.col.f32.f16.f16.f32 " \
        "{%0,%1,%2,%3},{%4,%5,%6,%7},{%8,%9},{%0,%1,%2,%3};" \
        : "+f"(d0), "+f"(d1), "+f"(d2), "+f"(d3) \
        : "r"(a0), "r"(a1), "r"(a2), "r"(a3), "r"(b0), "r"(b1))

// ---------------------------------------------------------- prep_w: w_q * s_w -> fp16
__global__ void __launch_bounds__(256) prep_w_kernel(const int* __restrict__ wq,
                                                     const float* __restrict__ sw) {
    unsigned gid = blockIdx.x * 256u + threadIdx.x;     // 2M threads, 8 elems each
    unsigned o  = gid >> 9;
    unsigned k0 = (gid & 511u) << 3;
    float s = sw[(k0 >> 7) * OUT_F + o];
    const int4* p = reinterpret_cast<const int4*>(wq + (size_t)o * IN_F + k0);
    int4 a = p[0], b = p[1];
    __half2 h0 = __floats2half2_rn(a.x * s, a.y * s);
    __half2 h1 = __floats2half2_rn(a.z * s, a.w * s);
    __half2 h2 = __floats2half2_rn(b.x * s, b.y * s);
    __half2 h3 = __floats2half2_rn(b.z * s, b.w * s);
    uint4 v;
    v.x = *reinterpret_cast<uint32_t*>(&h0);
    v.y = *reinterpret_cast<uint32_t*>(&h1);
    v.z = *reinterpret_cast<uint32_t*>(&h2);
    v.w = *reinterpret_cast<uint32_t*>(&h3);
    *reinterpret_cast<uint4*>(g_wh + (size_t)o * IN_F + k0) = v;
}

// ---------------------------------------------------------- prep_x: permute + fp32->fp16
__global__ void __launch_bounds__(256) prep_x_kernel(const float* __restrict__ x,
                                                     const int* __restrict__ perm32) {
    __shared__ float row[IN_F];
    __shared__ int is64s;
    int m = blockIdx.x, tid = threadIdx.x;
    const float4* src = reinterpret_cast<const float4*>(x + (size_t)m * IN_F);
#pragma unroll
    for (int i = 0; i < 4; ++i)
        reinterpret_cast<float4*>(row)[tid + i * 256] = src[tid + i * 256];
    if (tid == 0) {
        // jnp int64 vs int32 detection: int64 LE => odd 32-bit words all zero.
        int acc = 0;
#pragma unroll
        for (int t = 1; t < 32; t += 2) acc |= perm32[t];
        is64s = (acc == 0) ? 1 : 0;
    }
    __syncthreads();
    const int sh = is64s;
    const int j0 = tid * 16;
    __half* dst = g_xh + (size_t)m * IN_F + j0;
#pragma unroll
    for (int h = 0; h < 2; ++h) {
        int jb = j0 + h * 8;
        float v[8];
#pragma unroll
        for (int i = 0; i < 8; ++i) v[i] = row[perm32[(jb + i) << sh]];
        __half2 p0 = __floats2half2_rn(v[0], v[1]);
        __half2 p1 = __floats2half2_rn(v[2], v[3]);
        __half2 p2 = __floats2half2_rn(v[4], v[5]);
        __half2 p3 = __floats2half2_rn(v[6], v[7]);
        uint4 u;
        u.x = *reinterpret_cast<uint32_t*>(&p0);
        u.y = *reinterpret_cast<uint32_t*>(&p1);
        u.z = *reinterpret_cast<uint32_t*>(&p2);
        u.w = *reinterpret_cast<uint32_t*>(&p3);
        *reinterpret_cast<uint4*>(dst + h * 8) = u;
    }
}

// ---------------------------------------------------------- GEMM: mma.sync (HMMA) f16->f32
// CTA tile 128(M) x 128(N) x 64(K). 128 threads = 4 warps in 2(M) x 2(N), warp tile 64x64.
// 3-stage cp.async pipeline. Stage = A(16KB) + B(16KB) = 32KB; 96KB total -> 2 CTAs/SM.
static constexpr int BK          = 64;
static constexpr int NITER       = IN_F / BK;       // 64
static constexpr uint32_t STAGE_BYTES = 32768;
static constexpr uint32_t GEMM_SMEM   = 3 * STAGE_BYTES;  // 98304

// Load one K-slice: A rows [m0,m0+128), B rows [n0,n0+128), cols [j*64, j*64+64)
__device__ __forceinline__ void load_stage(uint32_t sb, int m0, int n0, int j, int tid) {
    const int k0 = j * BK;
#pragma unroll
    for (int c = 0; c < 8; ++c) {                 // A: 128 rows x 8 chunks of 16B
        int idx = tid + c * 128;
        int row = idx >> 3, ch = idx & 7;
        cpa16(sb + sw128((uint32_t)row * 128u + (uint32_t)ch * 16u),
              g_xh + (size_t)(m0 + row) * IN_F + k0 + ch * 8);
    }
#pragma unroll
    for (int c = 0; c < 8; ++c) {                 // B
        int idx = tid + c * 128;
        int row = idx >> 3, ch = idx & 7;
        cpa16(sb + 16384u + sw128((uint32_t)row * 128u + (uint32_t)ch * 16u),
              g_wh + (size_t)(n0 + row) * IN_F + k0 + ch * 8);
    }
}

__device__ __forceinline__ void compute_stage(uint32_t sA, uint32_t sB,
                                              int arow_l, int a_c, int brow_l, int b_c,
                                              int wm, int wn, float acc[4][8][4]) {
#pragma unroll
    for (int ks = 0; ks < 4; ++ks) {              // 4 k-steps of 16
        uint32_t a[4][4], b[4][4];
#pragma unroll
        for (int mi = 0; mi < 4; ++mi) {
            uint32_t off = (uint32_t)((wm * 64 + mi * 16 + arow_l) * 128 + (ks * 2 + a_c) * 16);
            LDSM4(a[mi][0], a[mi][1], a[mi][2], a[mi][3], sA + sw128(off));
        }
#pragma unroll
        for (int nb = 0; nb < 4; ++nb) {
            uint32_t off = (uint32_t)((wn * 64 + nb * 16 + brow_l) * 128 + (ks * 2 + b_c) * 16);
            LDSM4(b[nb][0], b[nb][1], b[nb][2], b[nb][3], sB + sw128(off));
        }
#pragma unroll
        for (int mi = 0; mi < 4; ++mi)
#pragma unroll
            for (int ni = 0; ni < 8; ++ni) {
                uint32_t b0 = b[ni >> 1][(ni & 1) * 2];
                uint32_t b1 = b[ni >> 1][(ni & 1) * 2 + 1];
                MMA16816(acc[mi][ni][0], acc[mi][ni][1], acc[mi][ni][2], acc[mi][ni][3],
                         a[mi][0], a[mi][1], a[mi][2], a[mi][3], b0, b1);
            }
    }
}

__global__ void __launch_bounds__(128, 2) gemm_kernel(const float* __restrict__ bias,
                                                      float* __restrict__ out) {
    extern __shared__ char smem[];
    const uint32_t sbase = smem_u32(smem);
    const int tid  = threadIdx.x;
    const int lane = tid & 31, wid = tid >> 5;
    const int wm = wid & 1, wn = wid >> 1;        // 2 x 2 warp grid
    const int n0 = blockIdx.x * 128, m0 = blockIdx.y * 128;

    // ldmatrix per-lane addressing constants
    // A (m16k16 regions): lanes 0-7 rows 0-7 @k0 | 8-15 rows 8-15 @k0 | 16-23 rows 0-7 @k8 | 24-31 rows 8-15 @k8
    const int arow_l = (lane & 7) + ((lane >> 3) & 1) * 8;
    const int a_c    = lane >> 4;
    // B (k16n16 regions, [n][k] layout): 0-7 n0-7@k0 | 8-15 n0-7@k8 | 16-23 n8-15@k0 | 24-31 n8-15@k8
    const int brow_l = (lane & 7) + ((lane >> 4) & 1) * 8;
    const int b_c    = (lane >> 3) & 1;

    float acc[4][8][4];
#pragma unroll
    for (int i = 0; i < 4; ++i)
#pragma unroll
        for (int j = 0; j < 8; ++j)
#pragma unroll
            for (int q = 0; q < 4; ++q) acc[i][j][q] = 0.f;

    // prologue: stages 0, 1
    load_stage(sbase + 0 * STAGE_BYTES, m0, n0, 0, tid);
    asm volatile("cp.async.commit_group;" ::: "memory");
    load_stage(sbase + 1 * STAGE_BYTES, m0, n0, 1, tid);
    asm volatile("cp.async.commit_group;" ::: "memory");

    for (int it = 0; it < NITER; ++it) {
        asm volatile("cp.async.wait_group 1;" ::: "memory");
        __syncthreads();
        const int j = it + 2;
        if (j < NITER)
            load_stage(sbase + (uint32_t)(j % 3) * STAGE_BYTES, m0, n0, j, tid);
        asm volatile("cp.async.commit_group;" ::: "memory");   // one group per iter (maybe empty)

        const uint32_t sb = sbase + (uint32_t)(it % 3) * STAGE_BYTES;
        compute_stage(sb, sb + 16384u, arow_l, a_c, brow_l, b_c, wm, wn, acc);
    }

    // epilogue: bias + float2 stores
    const int ncol = n0 + wn * 64 + (lane & 3) * 2;
    const int mrow = m0 + wm * 64 + (lane >> 2);
#pragma unroll
    for (int mi = 0; mi < 4; ++mi) {
        float* r0 = out + (size_t)(mrow + mi * 16) * OUT_F;
        float* r1 = r0 + 8 * OUT_F;
#pragma unroll
        for (int ni = 0; ni < 8; ++ni) {
            float2 bv = *reinterpret_cast<const float2*>(bias + ncol + ni * 8);
            float2 v0, v1;
            v0.x = acc[mi][ni][0] + bv.x;
            v0.y = acc[mi][ni][1] + bv.y;
            v1.x = acc[mi][ni][2] + bv.x;
            v1.y = acc[mi][ni][3] + bv.y;
            *reinterpret_cast<float2*>(r0 + ncol + ni * 8) = v0;
            *reinterpret_cast<float2*>(r1 + ncol + ni * 8) = v1;
        }
    }
}

// ---------------------------------------------------------- launch
extern "C" void kernel_launch(void* const* d_in, const int* in_sizes, int n_in,
                              void* d_out, int out_size) {
    const float* x    = (const float*)d_in[0];
    const int*   wq   = (const int*)d_in[1];
    const float* sw   = (const float*)d_in[2];
    const int*   perm = (const int*)d_in[3];   // int32 or int64 — detected on device
    const float* bias = (const float*)d_in[4];
    float* out = (float*)d_out;

    prep_w_kernel<<<(OUT_F * (IN_F / 8)) / 256, 256>>>(wq, sw);   // 8192 blocks
    prep_x_kernel<<<MTOT, 256>>>(x, perm);

    cudaFuncSetAttribute(gemm_kernel, cudaFuncAttributeMaxDynamicSharedMemorySize, GEMM_SMEM);
    gemm_kernel<<<dim3(OUT_F / 128, MTOT / 128), 128, GEMM_SMEM>>>(bias, out);
}